// round 2
// baseline (speedup 1.0000x reference)
#include <cuda_runtime.h>
#include <math.h>

#define NB 4
#define NT 4096
#define NS 4096
#define ND 512
#define NH 8
#define NHD 64

// Scratch (allocation-free rule: __device__ globals)
__device__ float g_q[NB * NH * NT * NHD];
__device__ float g_k[NB * NH * NS * NHD];
__device__ float g_v[NB * NH * NS * NHD];
__device__ float g_attn[NB * NT * ND];

// ---------------------------------------------------------------------------
// GEMM: out[M,N] = A[M,K=512] * W[N,K=512]^T + bias[N]
// Tiles: 64x64, BK=16. 256 threads, 4x4 micro-tile per thread.
// head_layout=1: scatter into [B,H,T,64] (N-block == head since BN=64==hd)
// ---------------------------------------------------------------------------
__global__ __launch_bounds__(256)
void gemm_bias_kernel(const float* __restrict__ A, const float* __restrict__ W,
                      const float* __restrict__ bias, float* __restrict__ out,
                      int head_layout)
{
    __shared__ float As[16][64];   // [k][m]
    __shared__ float Bs[16][64];   // [k][n]
    const int K = ND;
    const int tid = threadIdx.x;
    const int tx = tid & 15;       // n micro
    const int ty = tid >> 4;       // m micro
    const int m0 = blockIdx.y * 64;
    const int n0 = blockIdx.x * 64;
    const int lr = tid >> 2;       // 0..63 tile row for loads
    const int lc = tid & 3;        // 0..3  float4 column for loads

    const float* Ap = A + (size_t)(m0 + lr) * K + lc * 4;
    const float* Wp = W + (size_t)(n0 + lr) * K + lc * 4;

    float acc[4][4];
#pragma unroll
    for (int i = 0; i < 4; i++)
#pragma unroll
        for (int j = 0; j < 4; j++) acc[i][j] = 0.f;

    for (int k0 = 0; k0 < K; k0 += 16) {
        float4 av = *(const float4*)(Ap + k0);
        float4 wv = *(const float4*)(Wp + k0);
        __syncthreads();   // previous iteration's reads complete
        As[lc * 4 + 0][lr] = av.x;  As[lc * 4 + 1][lr] = av.y;
        As[lc * 4 + 2][lr] = av.z;  As[lc * 4 + 3][lr] = av.w;
        Bs[lc * 4 + 0][lr] = wv.x;  Bs[lc * 4 + 1][lr] = wv.y;
        Bs[lc * 4 + 2][lr] = wv.z;  Bs[lc * 4 + 3][lr] = wv.w;
        __syncthreads();
#pragma unroll
        for (int kk = 0; kk < 16; kk++) {
            float4 a4 = *(const float4*)&As[kk][ty * 4];
            float4 b4 = *(const float4*)&Bs[kk][tx * 4];
            float af[4] = {a4.x, a4.y, a4.z, a4.w};
            float bf[4] = {b4.x, b4.y, b4.z, b4.w};
#pragma unroll
            for (int i = 0; i < 4; i++)
#pragma unroll
                for (int j = 0; j < 4; j++) acc[i][j] += af[i] * bf[j];
        }
    }

    const float4 bv = *(const float4*)(bias + n0 + tx * 4);
#pragma unroll
    for (int i = 0; i < 4; i++) {
        int m = m0 + ty * 4 + i;
        float4 o;
        o.x = acc[i][0] + bv.x;
        o.y = acc[i][1] + bv.y;
        o.z = acc[i][2] + bv.z;
        o.w = acc[i][3] + bv.w;
        if (head_layout) {
            int bb = m >> 12;       // m / 4096 (T)
            int t  = m & 4095;
            int h  = n0 >> 6;       // head index
            *(float4*)(out + ((size_t)((bb * NH + h) * NT + t)) * NHD + tx * 4) = o;
        } else {
            *(float4*)(out + (size_t)m * ND + n0 + tx * 4) = o;
        }
    }
}

// ---------------------------------------------------------------------------
// Flash attention (fp32 SIMT): one CTA per (b, h, 64-row T tile).
// Streams S in 64-tiles: Q^T/K^T/V in smem (48KB), online softmax in regs,
// K-tile smem reused for the P tile. 16-lane shfl row reductions.
// Each thread loads 4 float4s per 64x64 tile (4096 floats / 256 threads).
// ---------------------------------------------------------------------------
__global__ __launch_bounds__(256)
void attn_kernel(const float* __restrict__ Q, const float* __restrict__ Kg,
                 const float* __restrict__ Vg,
                 const unsigned char* __restrict__ mask,
                 float* __restrict__ attn)
{
    __shared__ float Qs[64 * 64];   // [k][t-row], pre-scaled by 1/sqrt(hd)
    __shared__ float KPs[64 * 64];  // [k][s-col] for QK^T, then [t-row][s] as P
    __shared__ float Vs[64 * 64];   // [s][c]

    const int b  = blockIdx.z;
    const int h  = blockIdx.y;
    const int t0 = blockIdx.x * 64;
    const int tid = threadIdx.x;
    const int tx = tid & 15;        // score col / O col micro
    const int ty = tid >> 4;        // row micro
    const int lr = tid >> 2;        // 0..63 tile row for loads
    const int lc = tid & 3;         // base float4 column

    const float* Qp = Q  + ((size_t)(b * NH + h) * NT + t0) * NHD;
    const float* Kp = Kg + (size_t)(b * NH + h) * NS * NHD;
    const float* Vp = Vg + (size_t)(b * NH + h) * NS * NHD;
    const unsigned char* mp = mask + (size_t)b * NS;

    {   // load full Q tile (64x64), transposed + scaled: 4 float4s per thread
        const float sc = 0.125f;    // 1/sqrt(64)
#pragma unroll
        for (int c = 0; c < 4; c++) {
            int col = (lc + 4 * c) * 4;          // 0..60 step 4
            float4 qv = *(const float4*)(Qp + (size_t)lr * NHD + col);
            Qs[(col + 0) * 64 + lr] = qv.x * sc;
            Qs[(col + 1) * 64 + lr] = qv.y * sc;
            Qs[(col + 2) * 64 + lr] = qv.z * sc;
            Qs[(col + 3) * 64 + lr] = qv.w * sc;
        }
    }

    float m_i[4], l_i[4], O[4][4];
#pragma unroll
    for (int i = 0; i < 4; i++) {
        m_i[i] = -INFINITY; l_i[i] = 0.f;
#pragma unroll
        for (int j = 0; j < 4; j++) O[i][j] = 0.f;
    }

    for (int s0 = 0; s0 < NS; s0 += 64) {
        float4 kv[4], vv[4];
#pragma unroll
        for (int c = 0; c < 4; c++) {
            int col = (lc + 4 * c) * 4;
            kv[c] = *(const float4*)(Kp + (size_t)(s0 + lr) * NHD + col);
            vv[c] = *(const float4*)(Vp + (size_t)(s0 + lr) * NHD + col);
        }
        unsigned char mloc[4];
#pragma unroll
        for (int j = 0; j < 4; j++) mloc[j] = mp[s0 + tx * 4 + j];

        __syncthreads();   // previous PV reads of KPs/Vs complete
#pragma unroll
        for (int c = 0; c < 4; c++) {
            int col = (lc + 4 * c) * 4;
            KPs[(col + 0) * 64 + lr] = kv[c].x;
            KPs[(col + 1) * 64 + lr] = kv[c].y;
            KPs[(col + 2) * 64 + lr] = kv[c].z;
            KPs[(col + 3) * 64 + lr] = kv[c].w;
            *(float4*)&Vs[lr * 64 + col] = vv[c];
        }
        __syncthreads();

        // ---- QK^T: 4x4 scores per thread (rows ty*4+i, cols tx*4+j) ----
        float sreg[4][4];
#pragma unroll
        for (int i = 0; i < 4; i++)
#pragma unroll
            for (int j = 0; j < 4; j++) sreg[i][j] = 0.f;
#pragma unroll 8
        for (int k = 0; k < 64; k++) {
            float4 a4 = *(const float4*)&Qs[k * 64 + ty * 4];
            float4 b4 = *(const float4*)&KPs[k * 64 + tx * 4];
            float af[4] = {a4.x, a4.y, a4.z, a4.w};
            float bf[4] = {b4.x, b4.y, b4.z, b4.w};
#pragma unroll
            for (int i = 0; i < 4; i++)
#pragma unroll
                for (int j = 0; j < 4; j++) sreg[i][j] += af[i] * bf[j];
        }
#pragma unroll
        for (int j = 0; j < 4; j++) {
            if (mloc[j]) {
                sreg[0][j] = -INFINITY; sreg[1][j] = -INFINITY;
                sreg[2][j] = -INFINITY; sreg[3][j] = -INFINITY;
            }
        }

        __syncthreads();   // all QK^T reads of KPs done; safe to overwrite with P

        // ---- online softmax per row (16 threads with same ty share a row) ----
#pragma unroll
        for (int i = 0; i < 4; i++) {
            float tm = fmaxf(fmaxf(sreg[i][0], sreg[i][1]),
                             fmaxf(sreg[i][2], sreg[i][3]));
#pragma unroll
            for (int off = 1; off < 16; off <<= 1)
                tm = fmaxf(tm, __shfl_xor_sync(0xffffffffu, tm, off));
            float mnew  = fmaxf(m_i[i], tm);
            float msafe = (mnew == -INFINITY) ? 0.f : mnew;  // fully-masked row -> 0s
            float ts = 0.f;
#pragma unroll
            for (int j = 0; j < 4; j++) {
                float p = __expf(sreg[i][j] - msafe);
                sreg[i][j] = p;
                ts += p;
            }
#pragma unroll
            for (int off = 1; off < 16; off <<= 1)
                ts += __shfl_xor_sync(0xffffffffu, ts, off);
            float f = __expf(m_i[i] - msafe);
            l_i[i] = l_i[i] * f + ts;
            m_i[i] = mnew;
#pragma unroll
            for (int j = 0; j < 4; j++) O[i][j] *= f;
            // store P row chunk: natural [row][s] layout, conflict-free float4
            *(float4*)&KPs[(ty * 4 + i) * 64 + tx * 4] =
                make_float4(sreg[i][0], sreg[i][1], sreg[i][2], sreg[i][3]);
        }
        __syncthreads();   // P visible

        // ---- O += P @ V ----
#pragma unroll 8
        for (int s = 0; s < 64; s++) {
            float p0 = KPs[(ty * 4 + 0) * 64 + s];
            float p1 = KPs[(ty * 4 + 1) * 64 + s];
            float p2 = KPs[(ty * 4 + 2) * 64 + s];
            float p3 = KPs[(ty * 4 + 3) * 64 + s];
            float4 v4 = *(const float4*)&Vs[s * 64 + tx * 4];
            O[0][0] += p0 * v4.x; O[0][1] += p0 * v4.y; O[0][2] += p0 * v4.z; O[0][3] += p0 * v4.w;
            O[1][0] += p1 * v4.x; O[1][1] += p1 * v4.y; O[1][2] += p1 * v4.z; O[1][3] += p1 * v4.w;
            O[2][0] += p2 * v4.x; O[2][1] += p2 * v4.y; O[2][2] += p2 * v4.z; O[2][3] += p2 * v4.w;
            O[3][0] += p3 * v4.x; O[3][1] += p3 * v4.y; O[3][2] += p3 * v4.z; O[3][3] += p3 * v4.w;
        }
    }

    // ---- normalize + write attn in natural [B*T, D] layout for the Wo GEMM ----
#pragma unroll
    for (int i = 0; i < 4; i++) {
        float inv = (l_i[i] > 0.f) ? (1.0f / l_i[i]) : 0.f;
        float4 o = make_float4(O[i][0] * inv, O[i][1] * inv,
                               O[i][2] * inv, O[i][3] * inv);
        *(float4*)(attn + ((size_t)(b * NT + t0 + ty * 4 + i)) * ND
                        + h * NHD + tx * 4) = o;
    }
}

// ---------------------------------------------------------------------------
extern "C" void kernel_launch(void* const* d_in, const int* in_sizes, int n_in,
                              void* d_out, int out_size)
{
    const float* query = (const float*)d_in[0];
    const float* key   = (const float*)d_in[1];
    const float* value = (const float*)d_in[2];
    const unsigned char* mask = (const unsigned char*)d_in[3];
    const float* Wq = (const float*)d_in[4];
    const float* bq = (const float*)d_in[5];
    const float* Wk = (const float*)d_in[6];
    const float* bk = (const float*)d_in[7];
    const float* Wv = (const float*)d_in[8];
    const float* bv = (const float*)d_in[9];
    const float* Wo = (const float*)d_in[10];
    const float* bo = (const float*)d_in[11];
    float* out = (float*)d_out;

    float *qb, *kb, *vb, *ab;
    cudaGetSymbolAddress((void**)&qb, g_q);
    cudaGetSymbolAddress((void**)&kb, g_k);
    cudaGetSymbolAddress((void**)&vb, g_v);
    cudaGetSymbolAddress((void**)&ab, g_attn);

    dim3 blk(256);
    dim3 gg(ND / 64, (NB * NT) / 64);      // (8, 256)
    gemm_bias_kernel<<<gg, blk>>>(query, Wq, bq, qb, 1);
    gemm_bias_kernel<<<gg, blk>>>(key,   Wk, bk, kb, 1);
    gemm_bias_kernel<<<gg, blk>>>(value, Wv, bv, vb, 1);

    dim3 ga(NT / 64, NH, NB);              // (64, 8, 4)
    attn_kernel<<<ga, blk>>>(qb, kb, vb, mask, ab);

    gemm_bias_kernel<<<gg, blk>>>(ab, Wo, bo, out, 0);
}

// round 4
// speedup vs baseline: 1.5318x; 1.5318x over previous
#include <cuda_runtime.h>
#include <math.h>
#include <stdint.h>

#define NB 4
#define NT 4096
#define NS 4096
#define ND 512
#define NH 8
#define NHD 64

// Scratch (allocation-free rule: __device__ globals)
__device__ float g_q[NB * NH * NT * NHD];
__device__ float g_k[NB * NH * NS * NHD];
__device__ float g_v[NB * NH * NS * NHD];
__device__ float g_attn[NB * NT * ND];

// ===========================================================================
// helpers
// ===========================================================================
__device__ __forceinline__ uint32_t f2tf32(float x) {
    uint32_t r;
    asm("cvt.rna.tf32.f32 %0, %1;" : "=r"(r) : "f"(x));
    return r;
}
__device__ __forceinline__ float ex2f(float x) {
    float y;
    asm("ex2.approx.ftz.f32 %0, %1;" : "=f"(y) : "f"(x));
    return y;
}
// D += A * B  (m16n8k8 tf32, A row-major, B col-major)
__device__ __forceinline__ void mma_tf32(float* d, const uint32_t* a,
                                         uint32_t b0, uint32_t b1) {
    asm volatile(
        "mma.sync.aligned.m16n8k8.row.col.f32.tf32.tf32.f32 "
        "{%0,%1,%2,%3}, {%4,%5,%6,%7}, {%8,%9}, {%0,%1,%2,%3};"
        : "+f"(d[0]), "+f"(d[1]), "+f"(d[2]), "+f"(d[3])
        : "r"(a[0]), "r"(a[1]), "r"(a[2]), "r"(a[3]), "r"(b0), "r"(b1));
}

// ---------------------------------------------------------------------------
// GEMM: out[M,N] = A[M,K=512] * W[N,K=512]^T + bias[N]   (unchanged from R2)
// ---------------------------------------------------------------------------
__global__ __launch_bounds__(256)
void gemm_bias_kernel(const float* __restrict__ A, const float* __restrict__ W,
                      const float* __restrict__ bias, float* __restrict__ out,
                      int head_layout)
{
    __shared__ float As[16][64];
    __shared__ float Bs[16][64];
    const int K = ND;
    const int tid = threadIdx.x;
    const int tx = tid & 15;
    const int ty = tid >> 4;
    const int m0 = blockIdx.y * 64;
    const int n0 = blockIdx.x * 64;
    const int lr = tid >> 2;
    const int lc = tid & 3;

    const float* Ap = A + (size_t)(m0 + lr) * K + lc * 4;
    const float* Wp = W + (size_t)(n0 + lr) * K + lc * 4;

    float acc[4][4];
#pragma unroll
    for (int i = 0; i < 4; i++)
#pragma unroll
        for (int j = 0; j < 4; j++) acc[i][j] = 0.f;

    for (int k0 = 0; k0 < K; k0 += 16) {
        float4 av = *(const float4*)(Ap + k0);
        float4 wv = *(const float4*)(Wp + k0);
        __syncthreads();
        As[lc * 4 + 0][lr] = av.x;  As[lc * 4 + 1][lr] = av.y;
        As[lc * 4 + 2][lr] = av.z;  As[lc * 4 + 3][lr] = av.w;
        Bs[lc * 4 + 0][lr] = wv.x;  Bs[lc * 4 + 1][lr] = wv.y;
        Bs[lc * 4 + 2][lr] = wv.z;  Bs[lc * 4 + 3][lr] = wv.w;
        __syncthreads();
#pragma unroll
        for (int kk = 0; kk < 16; kk++) {
            float4 a4 = *(const float4*)&As[kk][ty * 4];
            float4 b4 = *(const float4*)&Bs[kk][tx * 4];
            float af[4] = {a4.x, a4.y, a4.z, a4.w};
            float bf[4] = {b4.x, b4.y, b4.z, b4.w};
#pragma unroll
            for (int i = 0; i < 4; i++)
#pragma unroll
                for (int j = 0; j < 4; j++) acc[i][j] += af[i] * bf[j];
        }
    }

    const float4 bv = *(const float4*)(bias + n0 + tx * 4);
#pragma unroll
    for (int i = 0; i < 4; i++) {
        int m = m0 + ty * 4 + i;
        float4 o;
        o.x = acc[i][0] + bv.x;
        o.y = acc[i][1] + bv.y;
        o.z = acc[i][2] + bv.z;
        o.w = acc[i][3] + bv.w;
        if (head_layout) {
            int bb = m >> 12;
            int t  = m & 4095;
            int h  = n0 >> 6;
            *(float4*)(out + ((size_t)((bb * NH + h) * NT + t)) * NHD + tx * 4) = o;
        } else {
            *(float4*)(out + (size_t)m * ND + n0 + tx * 4) = o;
        }
    }
}

// ---------------------------------------------------------------------------
// tf32 mma.sync flash attention.
// CTA = (b, h, 64-row T tile); 4 warps x 16 rows. KV streamed in 64-tiles.
// Q fragments in registers (log2-domain prescale). K smem [64][68] (QK
// B-frags conflict-free), V smem [64][72] (PV B-frags conflict-free),
// P reuses K smem. Online softmax: thread owns 2 rows, quad-shfl reduce.
// ---------------------------------------------------------------------------
__global__ __launch_bounds__(128)
void attn_kernel(const float* __restrict__ Q, const float* __restrict__ Kg,
                 const float* __restrict__ Vg,
                 const unsigned char* __restrict__ mask,
                 float* __restrict__ attn)
{
    __shared__ uint32_t Ksh[64][68];   // K tile (tf32 bits); reused as P
    __shared__ uint32_t Vsh[64][72];   // V tile (tf32 bits)
    __shared__ unsigned int MskW[16];  // 64 mask bytes

    const int b  = blockIdx.z;
    const int h  = blockIdx.y;
    const int t0 = blockIdx.x * 64;
    const int tid  = threadIdx.x;
    const int warp = tid >> 5;
    const int lane = tid & 31;
    const int g = lane >> 2;     // group id (row within fragment)
    const int q = lane & 3;      // thread-in-group
    const int w16 = warp * 16;

    const float* Qp = Q  + ((size_t)(b * NH + h) * NT + t0) * NHD;
    const float* Kp = Kg + (size_t)(b * NH + h) * NS * NHD;
    const float* Vp = Vg + (size_t)(b * NH + h) * NS * NHD;
    const unsigned char* mp = mask + (size_t)b * NS;
    const unsigned char* Msk = (const unsigned char*)MskW;

    // ---- Q fragments (registers, once per CTA), prescale 0.125*log2(e) ----
    uint32_t Qf[8][4];
    {
        const float qs = 0.125f * 1.4426950408889634f;
        const float* Qw = Qp + (size_t)w16 * NHD;
#pragma unroll
        for (int kc = 0; kc < 8; kc++) {
            Qf[kc][0] = f2tf32(Qw[(size_t)g       * NHD + kc * 8 + q]     * qs);
            Qf[kc][1] = f2tf32(Qw[(size_t)(g + 8) * NHD + kc * 8 + q]     * qs);
            Qf[kc][2] = f2tf32(Qw[(size_t)g       * NHD + kc * 8 + q + 4] * qs);
            Qf[kc][3] = f2tf32(Qw[(size_t)(g + 8) * NHD + kc * 8 + q + 4] * qs);
        }
    }

    float O[8][4];
#pragma unroll
    for (int nb = 0; nb < 8; nb++)
#pragma unroll
        for (int i = 0; i < 4; i++) O[nb][i] = 0.f;
    float m0 = -INFINITY, m1 = -INFINITY, l0 = 0.f, l1 = 0.f;

#pragma unroll 1
    for (int s0 = 0; s0 < NS; s0 += 64) {
        // ---- load K, V tiles into smem (tf32-rounded), plus mask ----
        {
            const int r  = tid >> 1;           // s-row 0..63
            const int cb = (tid & 1) * 32;     // hd col base
            const float* kp = Kp + (size_t)(s0 + r) * NHD + cb;
            const float* vp = Vp + (size_t)(s0 + r) * NHD + cb;
#pragma unroll
            for (int f = 0; f < 8; f++) {
                float4 kv = *(const float4*)(kp + f * 4);
                float4 vv = *(const float4*)(vp + f * 4);
                uint4 ku = make_uint4(f2tf32(kv.x), f2tf32(kv.y),
                                      f2tf32(kv.z), f2tf32(kv.w));
                uint4 vu = make_uint4(f2tf32(vv.x), f2tf32(vv.y),
                                      f2tf32(vv.z), f2tf32(vv.w));
                *(uint4*)&Ksh[r][cb + f * 4] = ku;
                *(uint4*)&Vsh[r][cb + f * 4] = vu;
            }
        }
        int anyLocal = 0;
        if (tid < 16) {
            unsigned int mw = *(const unsigned int*)(mp + s0 + tid * 4);
            MskW[tid] = mw;
            anyLocal = (mw != 0u);
        }
        int any = __syncthreads_or(anyLocal);

        // ---- QK^T: D[nb] = scores rows {g,g+8}+w16, cols nb*8+2q+{0,1} ----
        float D[8][4];
#pragma unroll
        for (int nb = 0; nb < 8; nb++) {
            D[nb][0] = 0.f; D[nb][1] = 0.f; D[nb][2] = 0.f; D[nb][3] = 0.f;
#pragma unroll
            for (int kc = 0; kc < 8; kc++) {
                uint32_t b0 = Ksh[nb * 8 + g][kc * 8 + q];
                uint32_t b1 = Ksh[nb * 8 + g][kc * 8 + q + 4];
                mma_tf32(D[nb], Qf[kc], b0, b1);
            }
        }

        // ---- mask ----
        if (any) {
#pragma unroll
            for (int nb = 0; nb < 8; nb++) {
                int c0 = nb * 8 + 2 * q;
                if (Msk[s0 >= 0 ? c0 : c0]) { D[nb][0] = -INFINITY; D[nb][2] = -INFINITY; }
                if (Msk[c0 + 1])            { D[nb][1] = -INFINITY; D[nb][3] = -INFINITY; }
            }
        }

        // ---- online softmax (log2 domain); rows r0=g, r1=g+8 ----
        float ml0 = -INFINITY, ml1 = -INFINITY;
#pragma unroll
        for (int nb = 0; nb < 8; nb++) {
            ml0 = fmaxf(ml0, fmaxf(D[nb][0], D[nb][1]));
            ml1 = fmaxf(ml1, fmaxf(D[nb][2], D[nb][3]));
        }
        ml0 = fmaxf(ml0, __shfl_xor_sync(0xffffffffu, ml0, 1));
        ml0 = fmaxf(ml0, __shfl_xor_sync(0xffffffffu, ml0, 2));
        ml1 = fmaxf(ml1, __shfl_xor_sync(0xffffffffu, ml1, 1));
        ml1 = fmaxf(ml1, __shfl_xor_sync(0xffffffffu, ml1, 2));

        float mn0 = fmaxf(m0, ml0), mn1 = fmaxf(m1, ml1);
        float ms0 = (mn0 == -INFINITY) ? 0.f : mn0;
        float ms1 = (mn1 == -INFINITY) ? 0.f : mn1;
        float sum0 = 0.f, sum1 = 0.f;
#pragma unroll
        for (int nb = 0; nb < 8; nb++) {
            float p00 = ex2f(D[nb][0] - ms0);
            float p01 = ex2f(D[nb][1] - ms0);
            float p10 = ex2f(D[nb][2] - ms1);
            float p11 = ex2f(D[nb][3] - ms1);
            sum0 += p00 + p01; sum1 += p10 + p11;
            D[nb][0] = p00; D[nb][1] = p01; D[nb][2] = p10; D[nb][3] = p11;
        }
        sum0 += __shfl_xor_sync(0xffffffffu, sum0, 1);
        sum0 += __shfl_xor_sync(0xffffffffu, sum0, 2);
        sum1 += __shfl_xor_sync(0xffffffffu, sum1, 1);
        sum1 += __shfl_xor_sync(0xffffffffu, sum1, 2);

        float f0 = ex2f(m0 - ms0);          // m0=-inf -> 0
        float f1 = ex2f(m1 - ms1);
        l0 = l0 * f0 + sum0;  m0 = mn0;
        l1 = l1 * f1 + sum1;  m1 = mn1;
#pragma unroll
        for (int nb = 0; nb < 8; nb++) {
            O[nb][0] *= f0; O[nb][1] *= f0;
            O[nb][2] *= f1; O[nb][3] *= f1;
        }

        __syncthreads();   // all QK reads of Ksh done; safe to overwrite with P
#pragma unroll
        for (int nb = 0; nb < 8; nb++) {
            int c = nb * 8 + 2 * q;
            Ksh[w16 + g][c]         = f2tf32(D[nb][0]);
            Ksh[w16 + g][c + 1]     = f2tf32(D[nb][1]);
            Ksh[w16 + g + 8][c]     = f2tf32(D[nb][2]);
            Ksh[w16 + g + 8][c + 1] = f2tf32(D[nb][3]);
        }
        __syncthreads();   // P visible

        // ---- O += P @ V ----
#pragma unroll
        for (int kc = 0; kc < 8; kc++) {
            uint32_t a[4];
            a[0] = Ksh[w16 + g][kc * 8 + q];
            a[1] = Ksh[w16 + g + 8][kc * 8 + q];
            a[2] = Ksh[w16 + g][kc * 8 + q + 4];
            a[3] = Ksh[w16 + g + 8][kc * 8 + q + 4];
#pragma unroll
            for (int nb = 0; nb < 8; nb++) {
                uint32_t b0 = Vsh[kc * 8 + q][nb * 8 + g];
                uint32_t b1 = Vsh[kc * 8 + q + 4][nb * 8 + g];
                mma_tf32(O[nb], a, b0, b1);
            }
        }
        __syncthreads();   // PV reads done before next tile overwrites K/V
    }

    // ---- epilogue: normalize, write [B*T, D] ----
    {
        float inv0 = (l0 > 0.f) ? (1.0f / l0) : 0.f;
        float inv1 = (l1 > 0.f) ? (1.0f / l1) : 0.f;
        float* o0 = attn + ((size_t)(b * NT + t0 + w16 + g))     * ND + h * NHD;
        float* o1 = attn + ((size_t)(b * NT + t0 + w16 + g + 8)) * ND + h * NHD;
#pragma unroll
        for (int nb = 0; nb < 8; nb++) {
            int c = nb * 8 + 2 * q;
            *(float2*)(o0 + c) = make_float2(O[nb][0] * inv0, O[nb][1] * inv0);
            *(float2*)(o1 + c) = make_float2(O[nb][2] * inv1, O[nb][3] * inv1);
        }
    }
}

// ---------------------------------------------------------------------------
extern "C" void kernel_launch(void* const* d_in, const int* in_sizes, int n_in,
                              void* d_out, int out_size)
{
    const float* query = (const float*)d_in[0];
    const float* key   = (const float*)d_in[1];
    const float* value = (const float*)d_in[2];
    const unsigned char* mask = (const unsigned char*)d_in[3];
    const float* Wq = (const float*)d_in[4];
    const float* bq = (const float*)d_in[5];
    const float* Wk = (const float*)d_in[6];
    const float* bk = (const float*)d_in[7];
    const float* Wv = (const float*)d_in[8];
    const float* bv = (const float*)d_in[9];
    const float* Wo = (const float*)d_in[10];
    const float* bo = (const float*)d_in[11];
    float* out = (float*)d_out;

    float *qb, *kb, *vb, *ab;
    cudaGetSymbolAddress((void**)&qb, g_q);
    cudaGetSymbolAddress((void**)&kb, g_k);
    cudaGetSymbolAddress((void**)&vb, g_v);
    cudaGetSymbolAddress((void**)&ab, g_attn);

    dim3 blk(256);
    dim3 gg(ND / 64, (NB * NT) / 64);      // (8, 256)
    gemm_bias_kernel<<<gg, blk>>>(query, Wq, bq, qb, 1);
    gemm_bias_kernel<<<gg, blk>>>(key,   Wk, bk, kb, 1);
    gemm_bias_kernel<<<gg, blk>>>(value, Wv, bv, vb, 1);

    dim3 ga(NT / 64, NH, NB);              // (64, 8, 4)
    attn_kernel<<<ga, 128>>>(qb, kb, vb, mask, ab);

    gemm_bias_kernel<<<gg, blk>>>(ab, Wo, bo, out, 0);
}

// round 5
// speedup vs baseline: 1.8554x; 1.2113x over previous
#include <cuda_runtime.h>
#include <cuda_fp16.h>
#include <math.h>
#include <stdint.h>

#define NB 4
#define NT 4096
#define NS 4096
#define ND 512
#define NH 8
#define NHD 64

// Scratch (allocation-free rule: __device__ globals)
__device__ float g_q[NB * NH * NT * NHD];
__device__ float g_k[NB * NH * NS * NHD];
__device__ float g_v[NB * NH * NS * NHD];
__device__ float g_attn[NB * NT * ND];

// ===========================================================================
// helpers
// ===========================================================================
__device__ __forceinline__ float ex2f(float x) {
    float y;
    asm("ex2.approx.ftz.f32 %0, %1;" : "=f"(y) : "f"(x));
    return y;
}
__device__ __forceinline__ uint32_t packh2(float lo, float hi) {
    __half2 h = __floats2half2_rn(lo, hi);
    return *reinterpret_cast<uint32_t*>(&h);
}
// D += A * B  (m16n8k16 fp16 in, fp32 accum; A row-major, B col-major)
__device__ __forceinline__ void mma_f16(float* d, const uint32_t* a,
                                        uint32_t b0, uint32_t b1) {
    asm volatile(
        "mma.sync.aligned.m16n8k16.row.col.f32.f16.f16.f32 "
        "{%0,%1,%2,%3}, {%4,%5,%6,%7}, {%8,%9}, {%0,%1,%2,%3};"
        : "+f"(d[0]), "+f"(d[1]), "+f"(d[2]), "+f"(d[3])
        : "r"(a[0]), "r"(a[1]), "r"(a[2]), "r"(a[3]), "r"(b0), "r"(b1));
}

// ---------------------------------------------------------------------------
// GEMM: out[M,N] = A[M,K=512] * W[N,K=512]^T + bias[N]   (unchanged from R2)
// ---------------------------------------------------------------------------
__global__ __launch_bounds__(256)
void gemm_bias_kernel(const float* __restrict__ A, const float* __restrict__ W,
                      const float* __restrict__ bias, float* __restrict__ out,
                      int head_layout)
{
    __shared__ float As[16][64];
    __shared__ float Bs[16][64];
    const int K = ND;
    const int tid = threadIdx.x;
    const int tx = tid & 15;
    const int ty = tid >> 4;
    const int m0 = blockIdx.y * 64;
    const int n0 = blockIdx.x * 64;
    const int lr = tid >> 2;
    const int lc = tid & 3;

    const float* Ap = A + (size_t)(m0 + lr) * K + lc * 4;
    const float* Wp = W + (size_t)(n0 + lr) * K + lc * 4;

    float acc[4][4];
#pragma unroll
    for (int i = 0; i < 4; i++)
#pragma unroll
        for (int j = 0; j < 4; j++) acc[i][j] = 0.f;

    for (int k0 = 0; k0 < K; k0 += 16) {
        float4 av = *(const float4*)(Ap + k0);
        float4 wv = *(const float4*)(Wp + k0);
        __syncthreads();
        As[lc * 4 + 0][lr] = av.x;  As[lc * 4 + 1][lr] = av.y;
        As[lc * 4 + 2][lr] = av.z;  As[lc * 4 + 3][lr] = av.w;
        Bs[lc * 4 + 0][lr] = wv.x;  Bs[lc * 4 + 1][lr] = wv.y;
        Bs[lc * 4 + 2][lr] = wv.z;  Bs[lc * 4 + 3][lr] = wv.w;
        __syncthreads();
#pragma unroll
        for (int kk = 0; kk < 16; kk++) {
            float4 a4 = *(const float4*)&As[kk][ty * 4];
            float4 b4 = *(const float4*)&Bs[kk][tx * 4];
            float af[4] = {a4.x, a4.y, a4.z, a4.w};
            float bf[4] = {b4.x, b4.y, b4.z, b4.w};
#pragma unroll
            for (int i = 0; i < 4; i++)
#pragma unroll
                for (int j = 0; j < 4; j++) acc[i][j] += af[i] * bf[j];
        }
    }

    const float4 bv = *(const float4*)(bias + n0 + tx * 4);
#pragma unroll
    for (int i = 0; i < 4; i++) {
        int m = m0 + ty * 4 + i;
        float4 o;
        o.x = acc[i][0] + bv.x;
        o.y = acc[i][1] + bv.y;
        o.z = acc[i][2] + bv.z;
        o.w = acc[i][3] + bv.w;
        if (head_layout) {
            int bb = m >> 12;
            int t  = m & 4095;
            int h  = n0 >> 6;
            *(float4*)(out + ((size_t)((bb * NH + h) * NT + t)) * NHD + tx * 4) = o;
        } else {
            *(float4*)(out + (size_t)m * ND + n0 + tx * 4) = o;
        }
    }
}

// ---------------------------------------------------------------------------
// fp16 m16n8k16 flash attention.
// CTA = (b, h, 64-row T tile); 4 warps x 16 rows; KV streamed in 64-tiles.
// Q fragments in registers (log2-domain prescale, fp16).
// K smem [64][72] fp16 row-major (QK B-frags = contiguous half2, bank 4g+q:
// conflict-free). V smem transposed [d][s] stride 72 (PV B-frags contiguous
// half2, conflict-free). P NEVER touches smem: the m16n8k16 f32 accumulator
// layout (rows {g,g+8}, cols {2q,2q+1}) packs directly into the next mma's
// A fragment. Online softmax: thread owns 2 rows, quad-shfl reduce.
// ---------------------------------------------------------------------------
__global__ __launch_bounds__(128)
void attn_kernel(const float* __restrict__ Q, const float* __restrict__ Kg,
                 const float* __restrict__ Vg,
                 const unsigned char* __restrict__ mask,
                 float* __restrict__ attn)
{
    __shared__ __half Ksh[64][72];     // K tile [s][d] fp16
    __shared__ __half VshT[64][72];    // V tile transposed [d][s] fp16
    __shared__ unsigned int MskW[16];  // 64 mask bytes

    const int b  = blockIdx.z;
    const int h  = blockIdx.y;
    const int t0 = blockIdx.x * 64;
    const int tid  = threadIdx.x;
    const int warp = tid >> 5;
    const int lane = tid & 31;
    const int g = lane >> 2;     // group id (row within fragment)
    const int q = lane & 3;      // thread-in-group
    const int w16 = warp * 16;

    const float* Qp = Q  + ((size_t)(b * NH + h) * NT + t0) * NHD;
    const float* Kp = Kg + (size_t)(b * NH + h) * NS * NHD;
    const float* Vp = Vg + (size_t)(b * NH + h) * NS * NHD;
    const unsigned char* mp = mask + (size_t)b * NS;
    const unsigned char* Msk = (const unsigned char*)MskW;

    // ---- Q fragments (fp16, registers, once per CTA); prescale 0.125*log2e
    //      a0=A[g][2q,2q+1], a1=A[g+8][2q,2q+1], a2=A[g][2q+8,+9], a3=A[g+8][..]
    uint32_t Qf[4][4];
    {
        const float qs = 0.125f * 1.4426950408889634f;
        const float* Q0 = Qp + (size_t)(w16 + g) * NHD;
        const float* Q1 = Qp + (size_t)(w16 + g + 8) * NHD;
#pragma unroll
        for (int kc = 0; kc < 4; kc++) {
            float2 x0 = *(const float2*)(Q0 + kc * 16 + 2 * q);
            float2 x1 = *(const float2*)(Q1 + kc * 16 + 2 * q);
            float2 x2 = *(const float2*)(Q0 + kc * 16 + 2 * q + 8);
            float2 x3 = *(const float2*)(Q1 + kc * 16 + 2 * q + 8);
            Qf[kc][0] = packh2(x0.x * qs, x0.y * qs);
            Qf[kc][1] = packh2(x1.x * qs, x1.y * qs);
            Qf[kc][2] = packh2(x2.x * qs, x2.y * qs);
            Qf[kc][3] = packh2(x3.x * qs, x3.y * qs);
        }
    }

    float O[8][4];
#pragma unroll
    for (int nb = 0; nb < 8; nb++)
#pragma unroll
        for (int i = 0; i < 4; i++) O[nb][i] = 0.f;
    float m0 = -INFINITY, m1 = -INFINITY, l0 = 0.f, l1 = 0.f;

#pragma unroll 1
    for (int s0 = 0; s0 < NS; s0 += 64) {
        // ---- produce K (fp16 [s][d]) and V^T (fp16 [d][s]) tiles ----
        {
            const int r  = tid >> 1;           // s-row 0..63
            const int cb = (tid & 1) * 32;     // d col base
            const float* kp = Kp + (size_t)(s0 + r) * NHD + cb;
            const float* vp = Vp + (size_t)(s0 + r) * NHD + cb;
#pragma unroll
            for (int f = 0; f < 8; f++) {
                float4 kv = *(const float4*)(kp + f * 4);
                float4 vv = *(const float4*)(vp + f * 4);
                int c = cb + f * 4;
                *(uint2*)&Ksh[r][c] =
                    make_uint2(packh2(kv.x, kv.y), packh2(kv.z, kv.w));
                VshT[c + 0][r] = __float2half_rn(vv.x);
                VshT[c + 1][r] = __float2half_rn(vv.y);
                VshT[c + 2][r] = __float2half_rn(vv.z);
                VshT[c + 3][r] = __float2half_rn(vv.w);
            }
        }
        int anyLocal = 0;
        if (tid < 16) {
            unsigned int mw = *(const unsigned int*)(mp + s0 + tid * 4);
            MskW[tid] = mw;
            anyLocal = (mw != 0u);
        }
        int any = __syncthreads_or(anyLocal);

        // ---- QK^T: D[nb] = scores rows {g,g+8}+w16, cols nb*8+2q+{0,1} ----
        float D[8][4];
#pragma unroll
        for (int nb = 0; nb < 8; nb++) {
            D[nb][0] = 0.f; D[nb][1] = 0.f; D[nb][2] = 0.f; D[nb][3] = 0.f;
            const __half* kr = &Ksh[nb * 8 + g][0];
#pragma unroll
            for (int kc = 0; kc < 4; kc++) {
                uint32_t b0 = *(const uint32_t*)(kr + kc * 16 + 2 * q);
                uint32_t b1 = *(const uint32_t*)(kr + kc * 16 + 2 * q + 8);
                mma_f16(D[nb], Qf[kc], b0, b1);
            }
        }

        // ---- mask ----
        if (any) {
#pragma unroll
            for (int nb = 0; nb < 8; nb++) {
                int c0 = nb * 8 + 2 * q;
                if (Msk[c0])     { D[nb][0] = -INFINITY; D[nb][2] = -INFINITY; }
                if (Msk[c0 + 1]) { D[nb][1] = -INFINITY; D[nb][3] = -INFINITY; }
            }
        }

        // ---- online softmax (log2 domain); rows r0=g, r1=g+8 ----
        float ml0 = -INFINITY, ml1 = -INFINITY;
#pragma unroll
        for (int nb = 0; nb < 8; nb++) {
            ml0 = fmaxf(ml0, fmaxf(D[nb][0], D[nb][1]));
            ml1 = fmaxf(ml1, fmaxf(D[nb][2], D[nb][3]));
        }
        ml0 = fmaxf(ml0, __shfl_xor_sync(0xffffffffu, ml0, 1));
        ml0 = fmaxf(ml0, __shfl_xor_sync(0xffffffffu, ml0, 2));
        ml1 = fmaxf(ml1, __shfl_xor_sync(0xffffffffu, ml1, 1));
        ml1 = fmaxf(ml1, __shfl_xor_sync(0xffffffffu, ml1, 2));

        float mn0 = fmaxf(m0, ml0), mn1 = fmaxf(m1, ml1);
        float ms0 = (mn0 == -INFINITY) ? 0.f : mn0;
        float ms1 = (mn1 == -INFINITY) ? 0.f : mn1;
        float sum0 = 0.f, sum1 = 0.f;
#pragma unroll
        for (int nb = 0; nb < 8; nb++) {
            float p00 = ex2f(D[nb][0] - ms0);
            float p01 = ex2f(D[nb][1] - ms0);
            float p10 = ex2f(D[nb][2] - ms1);
            float p11 = ex2f(D[nb][3] - ms1);
            sum0 += p00 + p01; sum1 += p10 + p11;
            D[nb][0] = p00; D[nb][1] = p01; D[nb][2] = p10; D[nb][3] = p11;
        }
        sum0 += __shfl_xor_sync(0xffffffffu, sum0, 1);
        sum0 += __shfl_xor_sync(0xffffffffu, sum0, 2);
        sum1 += __shfl_xor_sync(0xffffffffu, sum1, 1);
        sum1 += __shfl_xor_sync(0xffffffffu, sum1, 2);

        float f0 = ex2f(m0 - ms0);          // m0=-inf -> 0
        float f1 = ex2f(m1 - ms1);
        l0 = l0 * f0 + sum0;  m0 = mn0;
        l1 = l1 * f1 + sum1;  m1 = mn1;
#pragma unroll
        for (int nb = 0; nb < 8; nb++) {
            O[nb][0] *= f0; O[nb][1] *= f0;
            O[nb][2] *= f1; O[nb][3] *= f1;
        }

        // ---- O += P @ V : P packs straight from D registers (no smem) ----
#pragma unroll
        for (int kk = 0; kk < 4; kk++) {
            uint32_t a[4];
            a[0] = packh2(D[2 * kk][0],     D[2 * kk][1]);      // A[g][2q,2q+1]
            a[1] = packh2(D[2 * kk][2],     D[2 * kk][3]);      // A[g+8][2q,2q+1]
            a[2] = packh2(D[2 * kk + 1][0], D[2 * kk + 1][1]);  // A[g][2q+8,+9]
            a[3] = packh2(D[2 * kk + 1][2], D[2 * kk + 1][3]);  // A[g+8][2q+8,+9]
#pragma unroll
            for (int nb = 0; nb < 8; nb++) {
                const __half* vr = &VshT[nb * 8 + g][0];
                uint32_t b0 = *(const uint32_t*)(vr + kk * 16 + 2 * q);
                uint32_t b1 = *(const uint32_t*)(vr + kk * 16 + 2 * q + 8);
                mma_f16(O[nb], a, b0, b1);
            }
        }
        __syncthreads();   // QK/PV reads done before next tile overwrites K/V
    }

    // ---- epilogue: normalize, write [B*T, D] ----
    {
        float inv0 = (l0 > 0.f) ? (1.0f / l0) : 0.f;
        float inv1 = (l1 > 0.f) ? (1.0f / l1) : 0.f;
        float* o0 = attn + ((size_t)(b * NT + t0 + w16 + g))     * ND + h * NHD;
        float* o1 = attn + ((size_t)(b * NT + t0 + w16 + g + 8)) * ND + h * NHD;
#pragma unroll
        for (int nb = 0; nb < 8; nb++) {
            int c = nb * 8 + 2 * q;
            *(float2*)(o0 + c) = make_float2(O[nb][0] * inv0, O[nb][1] * inv0);
            *(float2*)(o1 + c) = make_float2(O[nb][2] * inv1, O[nb][3] * inv1);
        }
    }
}

// ---------------------------------------------------------------------------
extern "C" void kernel_launch(void* const* d_in, const int* in_sizes, int n_in,
                              void* d_out, int out_size)
{
    const float* query = (const float*)d_in[0];
    const float* key   = (const float*)d_in[1];
    const float* value = (const float*)d_in[2];
    const unsigned char* mask = (const unsigned char*)d_in[3];
    const float* Wq = (const float*)d_in[4];
    const float* bq = (const float*)d_in[5];
    const float* Wk = (const float*)d_in[6];
    const float* bk = (const float*)d_in[7];
    const float* Wv = (const float*)d_in[8];
    const float* bv = (const float*)d_in[9];
    const float* Wo = (const float*)d_in[10];
    const float* bo = (const float*)d_in[11];
    float* out = (float*)d_out;

    float *qb, *kb, *vb, *ab;
    cudaGetSymbolAddress((void**)&qb, g_q);
    cudaGetSymbolAddress((void**)&kb, g_k);
    cudaGetSymbolAddress((void**)&vb, g_v);
    cudaGetSymbolAddress((void**)&ab, g_attn);

    dim3 blk(256);
    dim3 gg(ND / 64, (NB * NT) / 64);      // (8, 256)
    gemm_bias_kernel<<<gg, blk>>>(query, Wq, bq, qb, 1);
    gemm_bias_kernel<<<gg, blk>>>(key,   Wk, bk, kb, 1);
    gemm_bias_kernel<<<gg, blk>>>(value, Wv, bv, vb, 1);

    dim3 ga(NT / 64, NH, NB);              // (64, 8, 4)
    attn_kernel<<<ga, 128>>>(qb, kb, vb, mask, ab);

    gemm_bias_kernel<<<gg, blk>>>(ab, Wo, bo, out, 0);
}

// round 6
// speedup vs baseline: 4.2396x; 2.2849x over previous
#include <cuda_runtime.h>
#include <cuda_fp16.h>
#include <math.h>
#include <stdint.h>

#define NB 4
#define NT 4096
#define NS 4096
#define ND 512
#define NH 8
#define NHD 64

// Scratch (allocation-free rule: __device__ globals)
__device__ __half g_q[NB * NH * NT * NHD];
__device__ __half g_k[NB * NH * NS * NHD];
__device__ __half g_v[NB * NH * NS * NHD];
__device__ float  g_attn[NB * NT * ND];

// ===========================================================================
// helpers
// ===========================================================================
__device__ __forceinline__ float ex2f(float x) {
    float y;
    asm("ex2.approx.ftz.f32 %0, %1;" : "=f"(y) : "f"(x));
    return y;
}
__device__ __forceinline__ uint32_t packh2(float lo, float hi) {
    __half2 h = __floats2half2_rn(lo, hi);
    return *reinterpret_cast<uint32_t*>(&h);
}
__device__ __forceinline__ uint32_t cvta_s(const void* p) {
    return (uint32_t)__cvta_generic_to_shared(p);
}
// D += A * B  (m16n8k16 fp16 in, fp32 accum; A row-major, B col-major)
__device__ __forceinline__ void mma_f16(float* d, const uint32_t* a,
                                        uint32_t b0, uint32_t b1) {
    asm volatile(
        "mma.sync.aligned.m16n8k16.row.col.f32.f16.f16.f32 "
        "{%0,%1,%2,%3}, {%4,%5,%6,%7}, {%8,%9}, {%0,%1,%2,%3};"
        : "+f"(d[0]), "+f"(d[1]), "+f"(d[2]), "+f"(d[3])
        : "r"(a[0]), "r"(a[1]), "r"(a[2]), "r"(a[3]), "r"(b0), "r"(b1));
}
__device__ __forceinline__ void ldsm4(uint32_t* r, uint32_t addr) {
    asm volatile("ldmatrix.sync.aligned.m8n8.x4.shared.b16 {%0,%1,%2,%3}, [%4];"
                 : "=r"(r[0]), "=r"(r[1]), "=r"(r[2]), "=r"(r[3]) : "r"(addr));
}
__device__ __forceinline__ void ldsm4t(uint32_t* r, uint32_t addr) {
    asm volatile("ldmatrix.sync.aligned.m8n8.x4.trans.shared.b16 {%0,%1,%2,%3}, [%4];"
                 : "=r"(r[0]), "=r"(r[1]), "=r"(r[2]), "=r"(r[3]) : "r"(addr));
}
__device__ __forceinline__ void cp16(uint32_t dst, const void* src) {
    asm volatile("cp.async.cg.shared.global [%0], [%1], 16;" :: "r"(dst), "l"(src));
}
#define CP_COMMIT() asm volatile("cp.async.commit_group;")
#define CP_WAIT1()  asm volatile("cp.async.wait_group 1;")
#define CP_WAIT0()  asm volatile("cp.async.wait_group 0;")

// ---------------------------------------------------------------------------
// Split-fp16 GEMM: out[M,N] = A[M,512] @ W[N,512]^T + bias[N]
// A = Ahi+Alo, W = Whi+Wlo (fp16 splits); D += Ahi*Whi + Ahi*Wlo + Alo*Whi
//   -> ~2^-22 element error (effectively fp32-accurate).
// CTA: 256 thr / 8 warps; tile M=64 (4 warps) x N=128 (2 warps); K-step 32.
// head_layout=1: write __half to [B,H,T,64]; else fp32 [M,512].
// ---------------------------------------------------------------------------
__global__ __launch_bounds__(256)
void gemm16_kernel(const float* __restrict__ A, const float* __restrict__ W,
                   const float* __restrict__ bias, void* __restrict__ outp,
                   int head_layout)
{
    __shared__ __half Ah[2][64][40];    // [hi/lo][m][k], pad 8
    __shared__ __half Wh[2][128][40];   // [hi/lo][n][k]

    const int tid  = threadIdx.x;
    const int warp = tid >> 5, lane = tid & 31;
    const int g = lane >> 2, q = lane & 3;
    const int wm = warp & 3, wn = warp >> 2;
    const int m0 = blockIdx.y * 64;
    const int n0 = blockIdx.x * 128;

    const int ar = tid >> 2, ac = (tid & 3) * 8;    // A tile: row, col-base
    const int wr = tid >> 1, wc = (tid & 1) * 16;   // W tile: row, col-base

    const float* Ap = A + (size_t)(m0 + ar) * ND + ac;
    const float* Wp = W + (size_t)(n0 + wr) * ND + wc;

    float D[8][4];
#pragma unroll
    for (int nb = 0; nb < 8; nb++)
#pragma unroll
        for (int i = 0; i < 4; i++) D[nb][i] = 0.f;

    float4 pa0 = *(const float4*)(Ap);
    float4 pa1 = *(const float4*)(Ap + 4);
    float4 pw0 = *(const float4*)(Wp);
    float4 pw1 = *(const float4*)(Wp + 4);
    float4 pw2 = *(const float4*)(Wp + 8);
    float4 pw3 = *(const float4*)(Wp + 12);

#pragma unroll 1
    for (int k0 = 0; k0 < ND; k0 += 32) {
        __syncthreads();   // previous stage's reads complete
        {   // convert + store A (8 vals) and W (16 vals) as hi/lo
            float va[8] = {pa0.x, pa0.y, pa0.z, pa0.w, pa1.x, pa1.y, pa1.z, pa1.w};
            __half hi[8], lo[8];
#pragma unroll
            for (int i = 0; i < 8; i++) {
                hi[i] = __float2half_rn(va[i]);
                lo[i] = __float2half_rn(va[i] - __half2float(hi[i]));
            }
            *(uint4*)&Ah[0][ar][ac] = *(uint4*)hi;
            *(uint4*)&Ah[1][ar][ac] = *(uint4*)lo;

            float vw[16] = {pw0.x, pw0.y, pw0.z, pw0.w, pw1.x, pw1.y, pw1.z, pw1.w,
                            pw2.x, pw2.y, pw2.z, pw2.w, pw3.x, pw3.y, pw3.z, pw3.w};
            __half whi[16], wlo[16];
#pragma unroll
            for (int i = 0; i < 16; i++) {
                whi[i] = __float2half_rn(vw[i]);
                wlo[i] = __float2half_rn(vw[i] - __half2float(whi[i]));
            }
            *(uint4*)&Wh[0][wr][wc]     = *(uint4*)whi;
            *(uint4*)&Wh[0][wr][wc + 8] = *(uint4*)(whi + 8);
            *(uint4*)&Wh[1][wr][wc]     = *(uint4*)wlo;
            *(uint4*)&Wh[1][wr][wc + 8] = *(uint4*)(wlo + 8);
        }
        __syncthreads();

        if (k0 + 32 < ND) {   // prefetch next stage (overlaps compute)
            pa0 = *(const float4*)(Ap + k0 + 32);
            pa1 = *(const float4*)(Ap + k0 + 36);
            pw0 = *(const float4*)(Wp + k0 + 32);
            pw1 = *(const float4*)(Wp + k0 + 36);
            pw2 = *(const float4*)(Wp + k0 + 40);
            pw3 = *(const float4*)(Wp + k0 + 44);
        }

#pragma unroll
        for (int kc = 0; kc < 2; kc++) {
            uint32_t ahf[4], alf[4];
            ldsm4(ahf, cvta_s(&Ah[0][wm * 16 + (lane & 15)][kc * 16 + (lane >> 4) * 8]));
            ldsm4(alf, cvta_s(&Ah[1][wm * 16 + (lane & 15)][kc * 16 + (lane >> 4) * 8]));
#pragma unroll
            for (int nbp = 0; nbp < 4; nbp++) {
                int row = wn * 64 + nbp * 16 + ((lane >> 4) & 1) * 8 + (lane & 7);
                int col = kc * 16 + ((lane >> 3) & 1) * 8;
                uint32_t bh[4], bl[4];
                ldsm4(bh, cvta_s(&Wh[0][row][col]));
                ldsm4(bl, cvta_s(&Wh[1][row][col]));
                mma_f16(D[2 * nbp],     ahf, bh[0], bh[1]);
                mma_f16(D[2 * nbp],     ahf, bl[0], bl[1]);
                mma_f16(D[2 * nbp],     alf, bh[0], bh[1]);
                mma_f16(D[2 * nbp + 1], ahf, bh[2], bh[3]);
                mma_f16(D[2 * nbp + 1], ahf, bl[2], bl[3]);
                mma_f16(D[2 * nbp + 1], alf, bh[2], bh[3]);
            }
        }
    }

    // ---- epilogue ----
    const float* bp = bias + n0 + wn * 64;
    const int mg = m0 + wm * 16 + g;
#pragma unroll
    for (int nb = 0; nb < 8; nb++) {
        int c = nb * 8 + 2 * q;
        float2 bb = *(const float2*)(bp + c);
        float o00 = D[nb][0] + bb.x, o01 = D[nb][1] + bb.y;   // row mg
        float o10 = D[nb][2] + bb.x, o11 = D[nb][3] + bb.y;   // row mg+8
        if (head_layout) {
            int n = n0 + wn * 64 + c;
            int h = n >> 6, d = n & 63;
            int bbi = mg >> 12, t = mg & 4095;
            __half* oh = (__half*)outp;
            size_t base = ((size_t)(bbi * NH + h) * NT + t) * NHD + d;
            *(__half2*)&oh[base]            = __floats2half2_rn(o00, o01);
            *(__half2*)&oh[base + 8 * NHD]  = __floats2half2_rn(o10, o11);
        } else {
            float* of = (float*)outp;
            size_t base = (size_t)mg * ND + n0 + wn * 64 + c;
            *(float2*)&of[base]            = make_float2(o00, o01);
            *(float2*)&of[base + 8 * ND]   = make_float2(o10, o11);
        }
    }
}

// ---------------------------------------------------------------------------
// fp16 flash attention v3: fp16 Q/K/V inputs, cp.async double-buffered K/V
// tiles, ldmatrix fragments (non-trans for QK^T, .trans for PV), P in regs.
// CTA = (b, h, 64-row T tile); 4 warps x 16 rows; KV streamed in 64-tiles.
// ---------------------------------------------------------------------------
__global__ __launch_bounds__(128)
void attn_kernel(const __half* __restrict__ Qh, const __half* __restrict__ Kh,
                 const __half* __restrict__ Vh,
                 const unsigned char* __restrict__ mask,
                 float* __restrict__ attn)
{
    __shared__ __half Ksh[2][64][72];   // K tile [s][d], double-buffered
    __shared__ __half Vsh[2][64][72];   // V tile [s][d], double-buffered
    __shared__ uint32_t MskW[2][16];    // 64 mask bytes / buffer

    const int b  = blockIdx.z;
    const int h  = blockIdx.y;
    const int t0 = blockIdx.x * 64;
    const int tid  = threadIdx.x;
    const int warp = tid >> 5;
    const int lane = tid & 31;
    const int g = lane >> 2;
    const int q = lane & 3;
    const int w16 = warp * 16;

    const __half* Kp = Kh + (size_t)(b * NH + h) * NS * NHD;
    const __half* Vp = Vh + (size_t)(b * NH + h) * NS * NHD;
    const unsigned char* mp = mask + (size_t)b * NS;

    // tile loader: 128 threads, 2 per row, 4x16B per (K,V) each + mask
    const int lrow = tid >> 1;
    const int lcol = (tid & 1) * 32;    // halves

    // ---- Q fragments (fp16 regs, once), scale 0.125*log2(e) via hmul2 ----
    uint32_t Qf[4][4];
    {
        const __half2 qs2 = __float2half2_rn(0.125f * 1.4426950408889634f);
        const __half* Q0 = Qh + ((size_t)(b * NH + h) * NT + t0 + w16 + g) * NHD;
        const __half* Q1 = Q0 + 8 * NHD;
#pragma unroll
        for (int kc = 0; kc < 4; kc++) {
            __half2 x0 = __hmul2(*(const __half2*)(Q0 + kc * 16 + 2 * q),     qs2);
            __half2 x1 = __hmul2(*(const __half2*)(Q1 + kc * 16 + 2 * q),     qs2);
            __half2 x2 = __hmul2(*(const __half2*)(Q0 + kc * 16 + 2 * q + 8), qs2);
            __half2 x3 = __hmul2(*(const __half2*)(Q1 + kc * 16 + 2 * q + 8), qs2);
            Qf[kc][0] = *(uint32_t*)&x0;
            Qf[kc][1] = *(uint32_t*)&x1;
            Qf[kc][2] = *(uint32_t*)&x2;
            Qf[kc][3] = *(uint32_t*)&x3;
        }
    }

    float O[8][4];
#pragma unroll
    for (int nb = 0; nb < 8; nb++)
#pragma unroll
        for (int i = 0; i < 4; i++) O[nb][i] = 0.f;
    float m0 = -INFINITY, m1 = -INFINITY, l0 = 0.f, l1 = 0.f;

    // ---- prologue: async-load tiles 0 and 1 ----
#pragma unroll
    for (int t = 0; t < 2; t++) {
        const __half* kg = Kp + (size_t)(t * 64 + lrow) * NHD + lcol;
        const __half* vg = Vp + (size_t)(t * 64 + lrow) * NHD + lcol;
        uint32_t kd = cvta_s(&Ksh[t][lrow][lcol]);
        uint32_t vd = cvta_s(&Vsh[t][lrow][lcol]);
#pragma unroll
        for (int j = 0; j < 4; j++) {
            cp16(kd + j * 16, kg + j * 8);
            cp16(vd + j * 16, vg + j * 8);
        }
        if (tid < 4) cp16(cvta_s(&MskW[t][tid * 4]), mp + t * 64 + tid * 16);
        CP_COMMIT();
    }

#pragma unroll 1
    for (int it = 0; it < NS / 64; it++) {
        const int cur = it & 1;
        if (it < NS / 64 - 1) { CP_WAIT1(); } else { CP_WAIT0(); }
        __syncthreads();   // tile `it` visible to all; prev buf reads done

        const unsigned char* Msk = (const unsigned char*)&MskW[cur][0];

        // ---- QK^T via ldmatrix(non-trans) B-frags ----
        float D[8][4];
#pragma unroll
        for (int nb = 0; nb < 8; nb++) {
            D[nb][0] = 0.f; D[nb][1] = 0.f; D[nb][2] = 0.f; D[nb][3] = 0.f;
        }
#pragma unroll
        for (int kc = 0; kc < 4; kc++) {
#pragma unroll
            for (int nbp = 0; nbp < 4; nbp++) {
                int row = nbp * 16 + ((lane >> 4) & 1) * 8 + (lane & 7);
                int col = kc * 16 + ((lane >> 3) & 1) * 8;
                uint32_t bf[4];
                ldsm4(bf, cvta_s(&Ksh[cur][row][col]));
                mma_f16(D[2 * nbp],     Qf[kc], bf[0], bf[1]);
                mma_f16(D[2 * nbp + 1], Qf[kc], bf[2], bf[3]);
            }
        }

        // ---- mask ----
#pragma unroll
        for (int nb = 0; nb < 8; nb++) {
            int c0 = nb * 8 + 2 * q;
            if (Msk[c0])     { D[nb][0] = -INFINITY; D[nb][2] = -INFINITY; }
            if (Msk[c0 + 1]) { D[nb][1] = -INFINITY; D[nb][3] = -INFINITY; }
        }

        // ---- online softmax (log2 domain); rows g, g+8 ----
        float ml0 = -INFINITY, ml1 = -INFINITY;
#pragma unroll
        for (int nb = 0; nb < 8; nb++) {
            ml0 = fmaxf(ml0, fmaxf(D[nb][0], D[nb][1]));
            ml1 = fmaxf(ml1, fmaxf(D[nb][2], D[nb][3]));
        }
        ml0 = fmaxf(ml0, __shfl_xor_sync(0xffffffffu, ml0, 1));
        ml0 = fmaxf(ml0, __shfl_xor_sync(0xffffffffu, ml0, 2));
        ml1 = fmaxf(ml1, __shfl_xor_sync(0xffffffffu, ml1, 1));
        ml1 = fmaxf(ml1, __shfl_xor_sync(0xffffffffu, ml1, 2));

        float mn0 = fmaxf(m0, ml0), mn1 = fmaxf(m1, ml1);
        float ms0 = (mn0 == -INFINITY) ? 0.f : mn0;
        float ms1 = (mn1 == -INFINITY) ? 0.f : mn1;
        float sum0 = 0.f, sum1 = 0.f;
#pragma unroll
        for (int nb = 0; nb < 8; nb++) {
            float p00 = ex2f(D[nb][0] - ms0);
            float p01 = ex2f(D[nb][1] - ms0);
            float p10 = ex2f(D[nb][2] - ms1);
            float p11 = ex2f(D[nb][3] - ms1);
            sum0 += p00 + p01; sum1 += p10 + p11;
            D[nb][0] = p00; D[nb][1] = p01; D[nb][2] = p10; D[nb][3] = p11;
        }
        sum0 += __shfl_xor_sync(0xffffffffu, sum0, 1);
        sum0 += __shfl_xor_sync(0xffffffffu, sum0, 2);
        sum1 += __shfl_xor_sync(0xffffffffu, sum1, 1);
        sum1 += __shfl_xor_sync(0xffffffffu, sum1, 2);

        float f0 = ex2f(m0 - ms0);
        float f1 = ex2f(m1 - ms1);
        l0 = l0 * f0 + sum0;  m0 = mn0;
        l1 = l1 * f1 + sum1;  m1 = mn1;
#pragma unroll
        for (int nb = 0; nb < 8; nb++) {
            O[nb][0] *= f0; O[nb][1] *= f0;
            O[nb][2] *= f1; O[nb][3] *= f1;
        }

        // ---- O += P @ V : A from D regs; B via ldmatrix.trans on V[s][d] ----
#pragma unroll
        for (int kk = 0; kk < 4; kk++) {
            uint32_t a[4];
            a[0] = packh2(D[2 * kk][0],     D[2 * kk][1]);
            a[1] = packh2(D[2 * kk][2],     D[2 * kk][3]);
            a[2] = packh2(D[2 * kk + 1][0], D[2 * kk + 1][1]);
            a[3] = packh2(D[2 * kk + 1][2], D[2 * kk + 1][3]);
#pragma unroll
            for (int nbp = 0; nbp < 4; nbp++) {
                int row = kk * 16 + ((lane >> 3) & 1) * 8 + (lane & 7);
                int col = nbp * 16 + ((lane >> 4) & 1) * 8;
                uint32_t bf[4];
                ldsm4t(bf, cvta_s(&Vsh[cur][row][col]));
                mma_f16(O[2 * nbp],     a, bf[0], bf[1]);
                mma_f16(O[2 * nbp + 1], a, bf[2], bf[3]);
            }
        }

        __syncthreads();   // all reads of buf `cur` done
        if (it + 2 < NS / 64) {   // async-load tile it+2 into buf `cur`
            int s0n = (it + 2) * 64;
            const __half* kg = Kp + (size_t)(s0n + lrow) * NHD + lcol;
            const __half* vg = Vp + (size_t)(s0n + lrow) * NHD + lcol;
            uint32_t kd = cvta_s(&Ksh[cur][lrow][lcol]);
            uint32_t vd = cvta_s(&Vsh[cur][lrow][lcol]);
#pragma unroll
            for (int j = 0; j < 4; j++) {
                cp16(kd + j * 16, kg + j * 8);
                cp16(vd + j * 16, vg + j * 8);
            }
            if (tid < 4) cp16(cvta_s(&MskW[cur][tid * 4]), mp + s0n + tid * 16);
            CP_COMMIT();
        }
    }

    // ---- epilogue: normalize, write [B*T, D] fp32 ----
    {
        float inv0 = (l0 > 0.f) ? (1.0f / l0) : 0.f;
        float inv1 = (l1 > 0.f) ? (1.0f / l1) : 0.f;
        float* o0 = attn + ((size_t)(b * NT + t0 + w16 + g))     * ND + h * NHD;
        float* o1 = attn + ((size_t)(b * NT + t0 + w16 + g + 8)) * ND + h * NHD;
#pragma unroll
        for (int nb = 0; nb < 8; nb++) {
            int c = nb * 8 + 2 * q;
            *(float2*)(o0 + c) = make_float2(O[nb][0] * inv0, O[nb][1] * inv0);
            *(float2*)(o1 + c) = make_float2(O[nb][2] * inv1, O[nb][3] * inv1);
        }
    }
}

// ---------------------------------------------------------------------------
extern "C" void kernel_launch(void* const* d_in, const int* in_sizes, int n_in,
                              void* d_out, int out_size)
{
    const float* query = (const float*)d_in[0];
    const float* key   = (const float*)d_in[1];
    const float* value = (const float*)d_in[2];
    const unsigned char* mask = (const unsigned char*)d_in[3];
    const float* Wq = (const float*)d_in[4];
    const float* bq = (const float*)d_in[5];
    const float* Wk = (const float*)d_in[6];
    const float* bk = (const float*)d_in[7];
    const float* Wv = (const float*)d_in[8];
    const float* bv = (const float*)d_in[9];
    const float* Wo = (const float*)d_in[10];
    const float* bo = (const float*)d_in[11];
    float* out = (float*)d_out;

    __half *qb, *kb, *vb;
    float* ab;
    cudaGetSymbolAddress((void**)&qb, g_q);
    cudaGetSymbolAddress((void**)&kb, g_k);
    cudaGetSymbolAddress((void**)&vb, g_v);
    cudaGetSymbolAddress((void**)&ab, g_attn);

    dim3 gg(ND / 128, (NB * NT) / 64);     // (4, 256)
    gemm16_kernel<<<gg, 256>>>(query, Wq, bq, qb, 1);
    gemm16_kernel<<<gg, 256>>>(key,   Wk, bk, kb, 1);
    gemm16_kernel<<<gg, 256>>>(value, Wv, bv, vb, 1);

    dim3 ga(NT / 64, NH, NB);              // (64, 8, 4)
    attn_kernel<<<ga, 128>>>(qb, kb, vb, mask, ab);

    gemm16_kernel<<<gg, 256>>>(ab, Wo, bo, out, 0);
}

// round 7
// speedup vs baseline: 4.3394x; 1.0235x over previous
#include <cuda_runtime.h>
#include <cuda_fp16.h>
#include <math.h>
#include <stdint.h>

#define NB 4
#define NT 4096
#define NS 4096
#define ND 512
#define NH 8
#define NHD 64

// Scratch (allocation-free rule: __device__ globals)
__device__ __half g_q[NB * NH * NT * NHD];
__device__ __half g_k[NB * NH * NS * NHD];
__device__ __half g_v[NB * NH * NS * NHD];
__device__ __half g_ah[3 * NB * NT * ND];   // hi split of query|key|value
__device__ __half g_al[3 * NB * NT * ND];   // lo split
__device__ __half g_wh[4 * ND * ND];        // hi split of Wq|Wk|Wv|Wo
__device__ __half g_wl[4 * ND * ND];
__device__ __half g_oh[NB * NT * ND];       // hi split of attention output
__device__ __half g_ol[NB * NT * ND];

// ===========================================================================
// helpers
// ===========================================================================
__device__ __forceinline__ float ex2f(float x) {
    float y;
    asm("ex2.approx.ftz.f32 %0, %1;" : "=f"(y) : "f"(x));
    return y;
}
__device__ __forceinline__ uint32_t packh2(float lo, float hi) {
    __half2 h = __floats2half2_rn(lo, hi);
    return *reinterpret_cast<uint32_t*>(&h);
}
__device__ __forceinline__ uint32_t cvta_s(const void* p) {
    return (uint32_t)__cvta_generic_to_shared(p);
}
// D += A * B  (m16n8k16 fp16 in, fp32 accum; A row-major, B col-major)
__device__ __forceinline__ void mma_f16(float* d, const uint32_t* a,
                                        uint32_t b0, uint32_t b1) {
    asm volatile(
        "mma.sync.aligned.m16n8k16.row.col.f32.f16.f16.f32 "
        "{%0,%1,%2,%3}, {%4,%5,%6,%7}, {%8,%9}, {%0,%1,%2,%3};"
        : "+f"(d[0]), "+f"(d[1]), "+f"(d[2]), "+f"(d[3])
        : "r"(a[0]), "r"(a[1]), "r"(a[2]), "r"(a[3]), "r"(b0), "r"(b1));
}
__device__ __forceinline__ void ldsm4(uint32_t* r, uint32_t addr) {
    asm volatile("ldmatrix.sync.aligned.m8n8.x4.shared.b16 {%0,%1,%2,%3}, [%4];"
                 : "=r"(r[0]), "=r"(r[1]), "=r"(r[2]), "=r"(r[3]) : "r"(addr));
}
__device__ __forceinline__ void ldsm4t(uint32_t* r, uint32_t addr) {
    asm volatile("ldmatrix.sync.aligned.m8n8.x4.trans.shared.b16 {%0,%1,%2,%3}, [%4];"
                 : "=r"(r[0]), "=r"(r[1]), "=r"(r[2]), "=r"(r[3]) : "r"(addr));
}
__device__ __forceinline__ void cp16(uint32_t dst, const void* src) {
    asm volatile("cp.async.cg.shared.global [%0], [%1], 16;" :: "r"(dst), "l"(src));
}
#define CP_COMMIT() asm volatile("cp.async.commit_group;")
#define CP_WAIT1()  asm volatile("cp.async.wait_group 1;")
#define CP_WAIT0()  asm volatile("cp.async.wait_group 0;")

// ---------------------------------------------------------------------------
// split: fp32 -> (hi fp16, lo fp16) with v = hi + lo + O(2^-22)
// ---------------------------------------------------------------------------
__global__ __launch_bounds__(256)
void split_kernel(const float* __restrict__ in, __half* __restrict__ hi,
                  __half* __restrict__ lo, int n)
{
    int i = (blockIdx.x * 256 + threadIdx.x) * 4;
    if (i >= n) return;
    float4 v = *(const float4*)(in + i);
    __half h[4], l[4];
    h[0] = __float2half_rn(v.x); l[0] = __float2half_rn(v.x - __half2float(h[0]));
    h[1] = __float2half_rn(v.y); l[1] = __float2half_rn(v.y - __half2float(h[1]));
    h[2] = __float2half_rn(v.z); l[2] = __float2half_rn(v.z - __half2float(h[2]));
    h[3] = __float2half_rn(v.w); l[3] = __float2half_rn(v.w - __half2float(h[3]));
    *(uint2*)(hi + i) = *(uint2*)h;
    *(uint2*)(lo + i) = *(uint2*)l;
}

// ---------------------------------------------------------------------------
// 3-term split-fp16 GEMM on pre-split inputs:
//   out[M,N] = (Ah+Al)[M,512] @ (Wh+Wl)[N,512]^T + bias, keeping
//   Ah*Wh + Ah*Wl + Al*Wh (error ~2^-22).
// CTA: 256 thr / 8 warps; tile M=128 (16 rows/warp) x N=64; K-step 64;
// cp.async double-buffered dynamic smem (110.6 KB).
// head_layout=1: fp16 out to [B,H,T,64] (N-tile == head); else fp32 [M,512].
// ---------------------------------------------------------------------------
#define GS_A  (128 * 72)                    // halves per A sub-tile
#define GS_W  (64 * 72)
#define GS_ST (2 * GS_A + 2 * GS_W)         // halves per stage = 27648

__global__ __launch_bounds__(256)
void gemm3_kernel(const __half* __restrict__ Ah, const __half* __restrict__ Al,
                  const __half* __restrict__ Wh, const __half* __restrict__ Wl,
                  const float* __restrict__ bias, void* __restrict__ outp,
                  int head_layout)
{
    extern __shared__ __half dsm[];

    const int tid  = threadIdx.x;
    const int warp = tid >> 5, lane = tid & 31;
    const int g = lane >> 2, q = lane & 3;
    const int m0 = blockIdx.y * 128;
    const int n0 = blockIdx.x * 64;

    // loaders
    const int arow = tid >> 1, acb = (tid & 1) * 32;   // A: 2 thr/row, 4 chunks
    const int wrow = tid >> 2, wcb = (tid & 3) * 16;   // W: 4 thr/row, 2 chunks

    const __half* Agh = Ah + (size_t)(m0 + arow) * ND + acb;
    const __half* Agl = Al + (size_t)(m0 + arow) * ND + acb;
    const __half* Wgh = Wh + (size_t)(n0 + wrow) * ND + wcb;
    const __half* Wgl = Wl + (size_t)(n0 + wrow) * ND + wcb;

    float D[8][4];
#pragma unroll
    for (int nb = 0; nb < 8; nb++)
#pragma unroll
        for (int i = 0; i < 4; i++) D[nb][i] = 0.f;

    auto load_stage = [&](int stage, int k0) {
        __half* base = dsm + (stage & 1) * GS_ST;
        uint32_t ah = cvta_s(base + arow * 72 + acb);
        uint32_t al = cvta_s(base + GS_A + arow * 72 + acb);
        uint32_t wh = cvta_s(base + 2 * GS_A + wrow * 72 + wcb);
        uint32_t wl = cvta_s(base + 2 * GS_A + GS_W + wrow * 72 + wcb);
#pragma unroll
        for (int j = 0; j < 4; j++) {
            cp16(ah + j * 16, Agh + k0 + j * 8);
            cp16(al + j * 16, Agl + k0 + j * 8);
        }
#pragma unroll
        for (int j = 0; j < 2; j++) {
            cp16(wh + j * 16, Wgh + k0 + j * 8);
            cp16(wl + j * 16, Wgl + k0 + j * 8);
        }
        CP_COMMIT();
    };

    load_stage(0, 0);
    load_stage(1, 64);

#pragma unroll 1
    for (int it = 0; it < ND / 64; it++) {
        const __half* base = dsm + (it & 1) * GS_ST;
        const __half* sAh = base;
        const __half* sAl = base + GS_A;
        const __half* sWh = base + 2 * GS_A;
        const __half* sWl = base + 2 * GS_A + GS_W;

        if (it < ND / 64 - 1) { CP_WAIT1(); } else { CP_WAIT0(); }
        __syncthreads();

#pragma unroll
        for (int kc = 0; kc < 4; kc++) {
            uint32_t ahf[4], alf[4];
            ldsm4(ahf, cvta_s(sAh + (warp * 16 + (lane & 15)) * 72
                              + kc * 16 + (lane >> 4) * 8));
            ldsm4(alf, cvta_s(sAl + (warp * 16 + (lane & 15)) * 72
                              + kc * 16 + (lane >> 4) * 8));
#pragma unroll
            for (int nbp = 0; nbp < 4; nbp++) {
                int row = nbp * 16 + ((lane >> 4) & 1) * 8 + (lane & 7);
                int col = kc * 16 + ((lane >> 3) & 1) * 8;
                uint32_t bh[4], bl[4];
                ldsm4(bh, cvta_s(sWh + row * 72 + col));
                ldsm4(bl, cvta_s(sWl + row * 72 + col));
                mma_f16(D[2 * nbp],     ahf, bh[0], bh[1]);
                mma_f16(D[2 * nbp + 1], ahf, bh[2], bh[3]);
                mma_f16(D[2 * nbp],     alf, bh[0], bh[1]);
                mma_f16(D[2 * nbp + 1], alf, bh[2], bh[3]);
                mma_f16(D[2 * nbp],     ahf, bl[0], bl[1]);
                mma_f16(D[2 * nbp + 1], ahf, bl[2], bl[3]);
            }
        }
        __syncthreads();
        if (it + 2 < ND / 64) load_stage(it + 2, (it + 2) * 64);
    }

    // ---- epilogue ----
    const float* bp = bias + n0;
    const int mg = m0 + warp * 16 + g;
#pragma unroll
    for (int nb = 0; nb < 8; nb++) {
        int c = nb * 8 + 2 * q;
        float2 bb = *(const float2*)(bp + c);
        float o00 = D[nb][0] + bb.x, o01 = D[nb][1] + bb.y;   // row mg
        float o10 = D[nb][2] + bb.x, o11 = D[nb][3] + bb.y;   // row mg+8
        if (head_layout) {
            int h = n0 >> 6;
            int bbi = mg >> 12, t = mg & 4095;
            __half* oh = (__half*)outp;
            size_t base = ((size_t)(bbi * NH + h) * NT + t) * NHD + c;
            *(__half2*)&oh[base]           = __floats2half2_rn(o00, o01);
            *(__half2*)&oh[base + 8 * NHD] = __floats2half2_rn(o10, o11);
        } else {
            float* of = (float*)outp;
            size_t base = (size_t)mg * ND + n0 + c;
            *(float2*)&of[base]          = make_float2(o00, o01);
            *(float2*)&of[base + 8 * ND] = make_float2(o10, o11);
        }
    }
}

// ---------------------------------------------------------------------------
// fp16 flash attention v4: cp.async double-buffered K/V, ldmatrix frags,
// P in regs, row-sums via P@ones MMA, skip-rescale, mask fast path.
// Emits hi/lo fp16 split of the output for the Wo GEMM.
// ---------------------------------------------------------------------------
__global__ __launch_bounds__(128)
void attn_kernel(const __half* __restrict__ Qh, const __half* __restrict__ Kh,
                 const __half* __restrict__ Vh,
                 const unsigned char* __restrict__ mask,
                 __half* __restrict__ outh, __half* __restrict__ outl)
{
    __shared__ __half Ksh[2][64][72];   // K tile [s][d], double-buffered
    __shared__ __half Vsh[2][64][72];   // V tile [s][d], double-buffered
    __shared__ uint32_t MskW[2][16];    // 64 mask bytes / buffer

    const int b  = blockIdx.z;
    const int h  = blockIdx.y;
    const int t0 = blockIdx.x * 64;
    const int tid  = threadIdx.x;
    const int warp = tid >> 5;
    const int lane = tid & 31;
    const int g = lane >> 2;
    const int q = lane & 3;
    const int w16 = warp * 16;
    const uint32_t ONES = 0x3C003C00u;   // half2(1,1)

    const __half* Kp = Kh + (size_t)(b * NH + h) * NS * NHD;
    const __half* Vp = Vh + (size_t)(b * NH + h) * NS * NHD;
    const unsigned char* mp = mask + (size_t)b * NS;

    const int lrow = tid >> 1;
    const int lcol = (tid & 1) * 32;

    // ---- Q fragments (fp16 regs, once), scale 0.125*log2(e) ----
    uint32_t Qf[4][4];
    {
        const __half2 qs2 = __float2half2_rn(0.125f * 1.4426950408889634f);
        const __half* Q0 = Qh + ((size_t)(b * NH + h) * NT + t0 + w16 + g) * NHD;
        const __half* Q1 = Q0 + 8 * NHD;
#pragma unroll
        for (int kc = 0; kc < 4; kc++) {
            __half2 x0 = __hmul2(*(const __half2*)(Q0 + kc * 16 + 2 * q),     qs2);
            __half2 x1 = __hmul2(*(const __half2*)(Q1 + kc * 16 + 2 * q),     qs2);
            __half2 x2 = __hmul2(*(const __half2*)(Q0 + kc * 16 + 2 * q + 8), qs2);
            __half2 x3 = __hmul2(*(const __half2*)(Q1 + kc * 16 + 2 * q + 8), qs2);
            Qf[kc][0] = *(uint32_t*)&x0;
            Qf[kc][1] = *(uint32_t*)&x1;
            Qf[kc][2] = *(uint32_t*)&x2;
            Qf[kc][3] = *(uint32_t*)&x3;
        }
    }

    float O[8][4];
#pragma unroll
    for (int nb = 0; nb < 8; nb++)
#pragma unroll
        for (int i = 0; i < 4; i++) O[nb][i] = 0.f;
    float m0 = -INFINITY, m1 = -INFINITY, l0 = 0.f, l1 = 0.f;

    // ---- prologue: async-load tiles 0 and 1 ----
#pragma unroll
    for (int t = 0; t < 2; t++) {
        const __half* kg = Kp + (size_t)(t * 64 + lrow) * NHD + lcol;
        const __half* vg = Vp + (size_t)(t * 64 + lrow) * NHD + lcol;
        uint32_t kd = cvta_s(&Ksh[t][lrow][lcol]);
        uint32_t vd = cvta_s(&Vsh[t][lrow][lcol]);
#pragma unroll
        for (int j = 0; j < 4; j++) {
            cp16(kd + j * 16, kg + j * 8);
            cp16(vd + j * 16, vg + j * 8);
        }
        if (tid < 4) cp16(cvta_s(&MskW[t][tid * 4]), mp + t * 64 + tid * 16);
        CP_COMMIT();
    }

#pragma unroll 1
    for (int it = 0; it < NS / 64; it++) {
        const int cur = it & 1;
        if (it < NS / 64 - 1) { CP_WAIT1(); } else { CP_WAIT0(); }
        // barrier + mask-nonzero reduction in one
        int any = __syncthreads_or((tid < 16) ? (int)(MskW[cur][tid] != 0u) : 0);

        // ---- QK^T via ldmatrix(non-trans) B-frags ----
        float D[8][4];
#pragma unroll
        for (int nb = 0; nb < 8; nb++) {
            D[nb][0] = 0.f; D[nb][1] = 0.f; D[nb][2] = 0.f; D[nb][3] = 0.f;
        }
#pragma unroll
        for (int kc = 0; kc < 4; kc++) {
#pragma unroll
            for (int nbp = 0; nbp < 4; nbp++) {
                int row = nbp * 16 + ((lane >> 4) & 1) * 8 + (lane & 7);
                int col = kc * 16 + ((lane >> 3) & 1) * 8;
                uint32_t bf[4];
                ldsm4(bf, cvta_s(&Ksh[cur][row][col]));
                mma_f16(D[2 * nbp],     Qf[kc], bf[0], bf[1]);
                mma_f16(D[2 * nbp + 1], Qf[kc], bf[2], bf[3]);
            }
        }

        // ---- mask (fast path skips when tile unmasked) ----
        if (any) {
            const unsigned char* Msk = (const unsigned char*)&MskW[cur][0];
#pragma unroll
            for (int nb = 0; nb < 8; nb++) {
                int c0 = nb * 8 + 2 * q;
                if (Msk[c0])     { D[nb][0] = -INFINITY; D[nb][2] = -INFINITY; }
                if (Msk[c0 + 1]) { D[nb][1] = -INFINITY; D[nb][3] = -INFINITY; }
            }
        }

        // ---- online softmax (log2 domain); rows g, g+8 ----
        float ml0 = -INFINITY, ml1 = -INFINITY;
#pragma unroll
        for (int nb = 0; nb < 8; nb++) {
            ml0 = fmaxf(ml0, fmaxf(D[nb][0], D[nb][1]));
            ml1 = fmaxf(ml1, fmaxf(D[nb][2], D[nb][3]));
        }
        ml0 = fmaxf(ml0, __shfl_xor_sync(0xffffffffu, ml0, 1));
        ml0 = fmaxf(ml0, __shfl_xor_sync(0xffffffffu, ml0, 2));
        ml1 = fmaxf(ml1, __shfl_xor_sync(0xffffffffu, ml1, 1));
        ml1 = fmaxf(ml1, __shfl_xor_sync(0xffffffffu, ml1, 2));

        float mn0 = fmaxf(m0, ml0), mn1 = fmaxf(m1, ml1);
        float ms0 = (mn0 == -INFINITY) ? 0.f : mn0;
        float ms1 = (mn1 == -INFINITY) ? 0.f : mn1;
#pragma unroll
        for (int nb = 0; nb < 8; nb++) {
            D[nb][0] = ex2f(D[nb][0] - ms0);
            D[nb][1] = ex2f(D[nb][1] - ms0);
            D[nb][2] = ex2f(D[nb][2] - ms1);
            D[nb][3] = ex2f(D[nb][3] - ms1);
        }

        float f0 = ex2f(m0 - ms0);   // exact 1.0 when max unchanged
        float f1 = ex2f(m1 - ms1);
        if (ml0 > m0 || ml1 > m1) {  // rescale only when a max moved
#pragma unroll
            for (int nb = 0; nb < 8; nb++) {
                O[nb][0] *= f0; O[nb][1] *= f0;
                O[nb][2] *= f1; O[nb][3] *= f1;
            }
        }
        m0 = mn0; m1 = mn1;

        // ---- O += P @ V ; row sums via P @ ones (consistent with fp16 P) ----
        float Ssum[4] = {0.f, 0.f, 0.f, 0.f};
#pragma unroll
        for (int kk = 0; kk < 4; kk++) {
            uint32_t a[4];
            a[0] = packh2(D[2 * kk][0],     D[2 * kk][1]);
            a[1] = packh2(D[2 * kk][2],     D[2 * kk][3]);
            a[2] = packh2(D[2 * kk + 1][0], D[2 * kk + 1][1]);
            a[3] = packh2(D[2 * kk + 1][2], D[2 * kk + 1][3]);
            mma_f16(Ssum, a, ONES, ONES);
#pragma unroll
            for (int nbp = 0; nbp < 4; nbp++) {
                int row = kk * 16 + ((lane >> 3) & 1) * 8 + (lane & 7);
                int col = nbp * 16 + ((lane >> 4) & 1) * 8;
                uint32_t bf[4];
                ldsm4t(bf, cvta_s(&Vsh[cur][row][col]));
                mma_f16(O[2 * nbp],     a, bf[0], bf[1]);
                mma_f16(O[2 * nbp + 1], a, bf[2], bf[3]);
            }
        }
        l0 = l0 * f0 + Ssum[0];
        l1 = l1 * f1 + Ssum[2];

        __syncthreads();   // all reads of buf `cur` done
        if (it + 2 < NS / 64) {
            int s0n = (it + 2) * 64;
            const __half* kg = Kp + (size_t)(s0n + lrow) * NHD + lcol;
            const __half* vg = Vp + (size_t)(s0n + lrow) * NHD + lcol;
            uint32_t kd = cvta_s(&Ksh[cur][lrow][lcol]);
            uint32_t vd = cvta_s(&Vsh[cur][lrow][lcol]);
#pragma unroll
            for (int j = 0; j < 4; j++) {
                cp16(kd + j * 16, kg + j * 8);
                cp16(vd + j * 16, vg + j * 8);
            }
            if (tid < 4) cp16(cvta_s(&MskW[cur][tid * 4]), mp + s0n + tid * 16);
            CP_COMMIT();
        }
    }

    // ---- epilogue: normalize, emit hi/lo fp16 split at [B*T, D] ----
    {
        float inv0 = (l0 > 0.f) ? (1.0f / l0) : 0.f;
        float inv1 = (l1 > 0.f) ? (1.0f / l1) : 0.f;
        size_t r0 = ((size_t)(b * NT + t0 + w16 + g))     * ND + h * NHD;
        size_t r1 = ((size_t)(b * NT + t0 + w16 + g + 8)) * ND + h * NHD;
#pragma unroll
        for (int nb = 0; nb < 8; nb++) {
            int c = nb * 8 + 2 * q;
            float x0 = O[nb][0] * inv0, x1 = O[nb][1] * inv0;
            float x2 = O[nb][2] * inv1, x3 = O[nb][3] * inv1;
            __half h0 = __float2half_rn(x0), h1 = __float2half_rn(x1);
            __half h2 = __float2half_rn(x2), h3 = __float2half_rn(x3);
            *(__half2*)&outh[r0 + c] = __halves2half2(h0, h1);
            *(__half2*)&outh[r1 + c] = __halves2half2(h2, h3);
            *(__half2*)&outl[r0 + c] = __floats2half2_rn(
                x0 - __half2float(h0), x1 - __half2float(h1));
            *(__half2*)&outl[r1 + c] = __floats2half2_rn(
                x2 - __half2float(h2), x3 - __half2float(h3));
        }
    }
}

// ---------------------------------------------------------------------------
extern "C" void kernel_launch(void* const* d_in, const int* in_sizes, int n_in,
                              void* d_out, int out_size)
{
    const float* query = (const float*)d_in[0];
    const float* key   = (const float*)d_in[1];
    const float* value = (const float*)d_in[2];
    const unsigned char* mask = (const unsigned char*)d_in[3];
    const float* Wq = (const float*)d_in[4];
    const float* bq = (const float*)d_in[5];
    const float* Wk = (const float*)d_in[6];
    const float* bk = (const float*)d_in[7];
    const float* Wv = (const float*)d_in[8];
    const float* bv = (const float*)d_in[9];
    const float* Wo = (const float*)d_in[10];
    const float* bo = (const float*)d_in[11];
    float* out = (float*)d_out;

    __half *qb, *kb, *vb, *ah, *al, *wh, *wl, *oh, *ol;
    cudaGetSymbolAddress((void**)&qb, g_q);
    cudaGetSymbolAddress((void**)&kb, g_k);
    cudaGetSymbolAddress((void**)&vb, g_v);
    cudaGetSymbolAddress((void**)&ah, g_ah);
    cudaGetSymbolAddress((void**)&al, g_al);
    cudaGetSymbolAddress((void**)&wh, g_wh);
    cudaGetSymbolAddress((void**)&wl, g_wl);
    cudaGetSymbolAddress((void**)&oh, g_oh);
    cudaGetSymbolAddress((void**)&ol, g_ol);

    const int smem3 = GS_ST * 2 * (int)sizeof(__half);   // 110592 B
    cudaFuncSetAttribute(gemm3_kernel,
                         cudaFuncAttributeMaxDynamicSharedMemorySize, smem3);

    const int NW = ND * ND;               // 262144 per weight
    const int NA = NB * NT * ND;          // 8388608 per activation

    // split weights (Wq|Wk|Wv|Wo) and activations (query|key|value)
    split_kernel<<<NW / 1024, 256>>>(Wq, wh + 0 * NW, wl + 0 * NW, NW);
    split_kernel<<<NW / 1024, 256>>>(Wk, wh + 1 * NW, wl + 1 * NW, NW);
    split_kernel<<<NW / 1024, 256>>>(Wv, wh + 2 * NW, wl + 2 * NW, NW);
    split_kernel<<<NW / 1024, 256>>>(Wo, wh + 3 * NW, wl + 3 * NW, NW);
    split_kernel<<<NA / 1024, 256>>>(query, ah + 0L * NA, al + 0L * NA, NA);
    split_kernel<<<NA / 1024, 256>>>(key,   ah + 1L * NA, al + 1L * NA, NA);
    split_kernel<<<NA / 1024, 256>>>(value, ah + 2L * NA, al + 2L * NA, NA);

    dim3 gg(ND / 64, (NB * NT) / 128);    // (8, 128)
    gemm3_kernel<<<gg, 256, smem3>>>(ah + 0L * NA, al + 0L * NA,
                                     wh + 0 * NW, wl + 0 * NW, bq, qb, 1);
    gemm3_kernel<<<gg, 256, smem3>>>(ah + 1L * NA, al + 1L * NA,
                                     wh + 1 * NW, wl + 1 * NW, bk, kb, 1);
    gemm3_kernel<<<gg, 256, smem3>>>(ah + 2L * NA, al + 2L * NA,
                                     wh + 2 * NW, wl + 2 * NW, bv, vb, 1);

    dim3 ga(NT / 64, NH, NB);             // (64, 8, 4)
    attn_kernel<<<ga, 128>>>(qb, kb, vb, mask, oh, ol);

    gemm3_kernel<<<gg, 256, smem3>>>(oh, ol, wh + 3 * NW, wl + 3 * NW,
                                     bo, out, 0);
}